// round 1
// baseline (speedup 1.0000x reference)
#include <cuda_runtime.h>
#include <cuda_bf16.h>

// Problem constants (hardcoded from reference):
//   PROJ=128, H=128, G=2, D=96, T=33, NEG=-1e9
//   x: (66,128,192) f32, edge_w: (192,192) f32
//   outputs: class (2,32,96,96) then dist (2,32,96), concatenated flat f32.

#define NEG_VAL (-1000000000.0f)

// Scratch (device globals -- no allocations allowed)
__device__ float g_E[2 * 33 * 96 * 128];   // node embeddings, row = g*33*96 + t*96 + i
__device__ float g_A[2 * 32 * 96 * 128];   // xne @ udW1[0:128]     row = g*32*96 + t*96 + i
__device__ float g_B[2 * 32 * 96 * 128];   // xce @ udW1[128:256]
__device__ float g_C[2 * 96 * 96 * 128];   // ee  @ udW1[256:288]   row = (g*96+i)*96 + j

// ---------------------------------------------------------------------------
// Kernel 1: node embeddings  E = relu(relu(x @ neW1 + b1) @ neW2 + b2)
// 8 rows per block, 128 threads. Row idx = g*33*96 + t*96 + i.
// ---------------------------------------------------------------------------
#define EROWS 8
__global__ void k_node_embed(const float* __restrict__ x,
                             const float* __restrict__ W1, const float* __restrict__ b1,
                             const float* __restrict__ W2, const float* __restrict__ b2) {
    int r0 = blockIdx.x * EROWS;
    int tid = threadIdx.x;  // 128
    __shared__ float xv[EROWS][128];
    __shared__ float y1[EROWS][128];

#pragma unroll
    for (int r = 0; r < EROWS; r++) {
        int idx = r0 + r;
        int g = idx / (33 * 96);
        int rem = idx % (33 * 96);
        int t = rem / 96;
        int i = rem % 96;
        // x[(g*33+t), h=tid, 96*g+i]
        xv[r][tid] = x[((g * 33 + t) * 128 + tid) * 192 + 96 * g + i];
    }
    __syncthreads();

    float acc[EROWS];
#pragma unroll
    for (int r = 0; r < EROWS; r++) acc[r] = b1[tid];
    for (int k = 0; k < 128; k++) {
        float w = W1[k * 128 + tid];
#pragma unroll
        for (int r = 0; r < EROWS; r++) acc[r] += xv[r][k] * w;
    }
#pragma unroll
    for (int r = 0; r < EROWS; r++) y1[r][tid] = fmaxf(acc[r], 0.0f);
    __syncthreads();

#pragma unroll
    for (int r = 0; r < EROWS; r++) acc[r] = b2[tid];
    for (int k = 0; k < 128; k++) {
        float w = W2[k * 128 + tid];
#pragma unroll
        for (int r = 0; r < EROWS; r++) acc[r] += y1[r][k] * w;
    }
#pragma unroll
    for (int r = 0; r < EROWS; r++) g_E[(r0 + r) * 128 + tid] = fmaxf(acc[r], 0.0f);
}

// ---------------------------------------------------------------------------
// Kernel 2: A/B projections + dist head.
// Row idx = g*32*96 + t*96 + i (6144 rows), 8 per block, 128 threads.
//   A = E[t+1,i] @ udW1[0:128],  B = E[t,i] @ udW1[128:256]
//   dist = mlp3([E[t,i], E[t+1,i]], dp*)
// ---------------------------------------------------------------------------
#define PROWS 8
__global__ void k_proj_dist(const float* __restrict__ udW1,
                            const float* __restrict__ dpW1, const float* __restrict__ dpb1,
                            const float* __restrict__ dpW2, const float* __restrict__ dpb2,
                            const float* __restrict__ dpW3, const float* __restrict__ dpb3,
                            float* __restrict__ dist_out) {
    int r0 = blockIdx.x * PROWS;
    int tid = threadIdx.x;  // 128
    int g = r0 / (32 * 96);
    int rem = r0 % (32 * 96);
    int t = rem / 96;
    int i0 = rem % 96;

    __shared__ float Ec[PROWS][128];
    __shared__ float En[PROWS][128];
    __shared__ float y1d[PROWS][128];

    for (int e = tid; e < PROWS * 128; e += 128) {
        int r = e >> 7, k = e & 127;
        Ec[r][k] = g_E[((g * 33 + t) * 96 + i0 + r) * 128 + k];
        En[r][k] = g_E[((g * 33 + t + 1) * 96 + i0 + r) * 128 + k];
    }
    __syncthreads();

    float accA[PROWS], accB[PROWS], accD[PROWS];
#pragma unroll
    for (int r = 0; r < PROWS; r++) { accA[r] = 0.0f; accB[r] = 0.0f; accD[r] = 0.0f; }

    for (int k = 0; k < 128; k++) {
        float wa = udW1[k * 128 + tid];
        float wb = udW1[(128 + k) * 128 + tid];
        float wc = dpW1[k * 128 + tid];
        float wd = dpW1[(128 + k) * 128 + tid];
#pragma unroll
        for (int r = 0; r < PROWS; r++) {
            accA[r] += En[r][k] * wa;
            accB[r] += Ec[r][k] * wb;
            accD[r] += Ec[r][k] * wc + En[r][k] * wd;
        }
    }
    float db1 = dpb1[tid];
#pragma unroll
    for (int r = 0; r < PROWS; r++) {
        g_A[(r0 + r) * 128 + tid] = accA[r];
        g_B[(r0 + r) * 128 + tid] = accB[r];
        y1d[r][tid] = fmaxf(accD[r] + db1, 0.0f);
    }
    __syncthreads();

    // dist layers 2+3: thread (r = tid>>4, q = tid&15) handles 4 n's
    int r = tid >> 4;
    int q = tid & 15;
    float s = 0.0f;
#pragma unroll
    for (int nn = 0; nn < 4; nn++) {
        int n = q * 4 + nn;
        float a = dpb2[n];
        for (int k = 0; k < 128; k++) a += y1d[r][k] * dpW2[k * 64 + n];
        s += fmaxf(a, 0.0f) * dpW3[n];
    }
#pragma unroll
    for (int off = 8; off; off >>= 1) s += __shfl_xor_sync(0xffffffffu, s, off);
    if (q == 0) dist_out[r0 + r] = s + dpb3[0];
}

// ---------------------------------------------------------------------------
// Kernel 3: edge MLP + C projection.
// One block per (g, i), 128 threads, all 96 j.
//   l1[q] = relu(ew*eeW1[q]+eeb1[q]); l2[q] = relu(l1@eeW2+eeb2)
//   C[g,i,j,:] = l2 @ udW1[256:288]
// ---------------------------------------------------------------------------
__global__ void k_ee_c(const float* __restrict__ edge_w,
                       const float* __restrict__ eeW1, const float* __restrict__ eeb1,
                       const float* __restrict__ eeW2, const float* __restrict__ eeb2,
                       const float* __restrict__ udW1) {
    int g = blockIdx.x / 96;
    int i = blockIdx.x % 96;
    int tid = threadIdx.x;  // 128

    __shared__ float l2s[96][33];
    __shared__ float w1s[32], b1s[32], b2s[32];
    __shared__ float w2s[32 * 32];
    __shared__ float w1cs[32 * 128];
    __shared__ float ews[96];

    if (tid < 32) { w1s[tid] = eeW1[tid]; b1s[tid] = eeb1[tid]; b2s[tid] = eeb2[tid]; }
    for (int e = tid; e < 1024; e += 128) w2s[e] = eeW2[e];
    for (int e = tid; e < 4096; e += 128) w1cs[e] = udW1[256 * 128 + e];
    if (tid < 96) ews[tid] = edge_w[(96 * g + i) * 192 + 96 * g + tid];
    __syncthreads();

    for (int e = tid; e < 96 * 32; e += 128) {
        int j = e >> 5, q = e & 31;
        float e0 = ews[j];
        float a = b2s[q];
#pragma unroll
        for (int p = 0; p < 32; p++) {
            float l1 = fmaxf(e0 * w1s[p] + b1s[p], 0.0f);
            a += l1 * w2s[p * 32 + q];
        }
        l2s[j][q] = fmaxf(a, 0.0f);
    }
    __syncthreads();

    float* Cout = g_C + (size_t)((g * 96 + i) * 96) * 128;
    for (int j = 0; j < 96; j++) {
        float a = 0.0f;
#pragma unroll
        for (int q = 0; q < 32; q++) a += l2s[j][q] * w1cs[q * 128 + tid];
        Cout[j * 128 + tid] = a;
    }
}

// ---------------------------------------------------------------------------
// Kernel 4 (dominant): per (g,t,i) compute logits[j=0..95].
//   h[j,k]   = relu(A[i,k] + B[j,k] + C[i,j,k] + b1[k])        (96 x 128)
//   y2[j,n]  = relu(h @ W2 + b2)                               (96 x 64)
//   logit[j] = y2 @ W3 + b3, masked where ew==0 && j!=i
// 256 threads: thread (ty=tid>>4, tx=tid&15) owns 6 j x 4 n accumulators.
// K streamed in 4 tiles of 32 through shared.
// ---------------------------------------------------------------------------
__global__ void __launch_bounds__(256) k_logits(const float* __restrict__ edge_w,
                                                const float* __restrict__ udb1,
                                                const float* __restrict__ udW2,
                                                const float* __restrict__ udb2,
                                                const float* __restrict__ udW3,
                                                const float* __restrict__ udb3,
                                                float* __restrict__ out) {
    int bid = blockIdx.x;                 // g*32*96 + t*96 + i
    int g = bid / (32 * 96);
    int rem = bid % (32 * 96);
    int t = rem / 96;
    int i = rem % 96;
    int tid = threadIdx.x;
    int tx = tid & 15;
    int ty = tid >> 4;

    __shared__ float sW2[128 * 64];       // 32 KB
    __shared__ float sh[32][97];          // h^T tile, odd-stride padded
    __shared__ float sA[128];
    __shared__ float sW3[64];
    __shared__ float sb2[64];
    __shared__ float ews[96];

    for (int e = tid; e < 128 * 64; e += 256) sW2[e] = udW2[e];
    if (tid < 128) sA[tid] = g_A[bid * 128 + tid] + udb1[tid];
    if (tid >= 128 && tid < 192) { int n = tid - 128; sW3[n] = udW3[n]; sb2[n] = udb2[n]; }
    if (tid >= 160) {
        int j = tid - 160;  // 96 entries
        ews[j] = edge_w[(96 * g + i) * 192 + 96 * g + j];
    }

    const float* Bb = g_B + (size_t)((g * 32 + t) * 96) * 128;
    const float* Cb = g_C + (size_t)((g * 96 + i) * 96) * 128;

    float acc[6][4];
#pragma unroll
    for (int jj = 0; jj < 6; jj++)
#pragma unroll
        for (int nn = 0; nn < 4; nn++) acc[jj][nn] = 0.0f;

    for (int kt = 0; kt < 4; kt++) {
        __syncthreads();  // guards sh reuse (and initial smem loads on kt==0)
        for (int e = tid; e < 96 * 32; e += 256) {
            int j = e >> 5, k = e & 31;
            int kk = kt * 32 + k;
            float v = sA[kk] + Bb[j * 128 + kk] + Cb[j * 128 + kk];
            sh[k][j] = fmaxf(v, 0.0f);
        }
        __syncthreads();
#pragma unroll 8
        for (int k = 0; k < 32; k++) {
            int kk = kt * 32 + k;
            float4 w = *reinterpret_cast<const float4*>(&sW2[kk * 64 + tx * 4]);
#pragma unroll
            for (int jj = 0; jj < 6; jj++) {
                float hv = sh[k][ty * 6 + jj];
                acc[jj][0] += hv * w.x;
                acc[jj][1] += hv * w.y;
                acc[jj][2] += hv * w.z;
                acc[jj][3] += hv * w.w;
            }
        }
    }

    float b3 = udb3[0];
#pragma unroll
    for (int jj = 0; jj < 6; jj++) {
        float s = 0.0f;
#pragma unroll
        for (int nn = 0; nn < 4; nn++) {
            int n = tx * 4 + nn;
            s += fmaxf(acc[jj][nn] + sb2[n], 0.0f) * sW3[n];
        }
#pragma unroll
        for (int off = 8; off; off >>= 1) s += __shfl_xor_sync(0xffffffffu, s, off);
        if (tx == 0) {
            int j = ty * 6 + jj;
            float L = s + b3;
            if (ews[j] == 0.0f && j != i) L = NEG_VAL;
            out[(size_t)bid * 96 + j] = L;
        }
    }
}

// ---------------------------------------------------------------------------
// Launch
// ---------------------------------------------------------------------------
extern "C" void kernel_launch(void* const* d_in, const int* in_sizes, int n_in,
                              void* d_out, int out_size) {
    // Weight block is the last 20 inputs regardless of whether scalar
    // 'no_graphs' appears in the input list.
    int w0 = n_in - 20;
    const float* x      = (const float*)d_in[0];
    const float* edge_w = (const float*)d_in[1];
    const float* neW1 = (const float*)d_in[w0 + 0];
    const float* neb1 = (const float*)d_in[w0 + 1];
    const float* neW2 = (const float*)d_in[w0 + 2];
    const float* neb2 = (const float*)d_in[w0 + 3];
    const float* eeW1 = (const float*)d_in[w0 + 4];
    const float* eeb1 = (const float*)d_in[w0 + 5];
    const float* eeW2 = (const float*)d_in[w0 + 6];
    const float* eeb2 = (const float*)d_in[w0 + 7];
    const float* udW1 = (const float*)d_in[w0 + 8];
    const float* udb1 = (const float*)d_in[w0 + 9];
    const float* udW2 = (const float*)d_in[w0 + 10];
    const float* udb2 = (const float*)d_in[w0 + 11];
    const float* udW3 = (const float*)d_in[w0 + 12];
    const float* udb3 = (const float*)d_in[w0 + 13];
    const float* dpW1 = (const float*)d_in[w0 + 14];
    const float* dpb1 = (const float*)d_in[w0 + 15];
    const float* dpW2 = (const float*)d_in[w0 + 16];
    const float* dpb2 = (const float*)d_in[w0 + 17];
    const float* dpW3 = (const float*)d_in[w0 + 18];
    const float* dpb3 = (const float*)d_in[w0 + 19];

    float* out = (float*)d_out;
    const int CLASS_N = 2 * 32 * 96 * 96;  // 589824
    float* dist_out = out + CLASS_N;

    // 1) node embeddings: 2*33*96 = 6336 rows, 8/block
    k_node_embed<<<6336 / EROWS, 128>>>(x, neW1, neb1, neW2, neb2);
    // 2) A/B projections + dist: 2*32*96 = 6144 rows, 8/block
    k_proj_dist<<<6144 / PROWS, 128>>>(udW1, dpW1, dpb1, dpW2, dpb2, dpW3, dpb3, dist_out);
    // 3) edge MLP + C: one block per (g,i)
    k_ee_c<<<2 * 96, 128>>>(edge_w, eeW1, eeb1, eeW2, eeb2, udW1);
    // 4) main logits kernel: one block per (g,t,i)
    k_logits<<<2 * 32 * 96, 256>>>(edge_w, udb1, udW2, udb2, udW3, udb3, out);
}

// round 2
// speedup vs baseline: 1.0186x; 1.0186x over previous
#include <cuda_runtime.h>
#include <cuda_bf16.h>

// Problem constants (hardcoded from reference):
//   PROJ=128, H=128, G=2, D=96, T=33, NEG=-1e9
//   x: (66,128,192) f32, edge_w: (192,192) f32
//   outputs: class (2,32,96,96) then dist (2,32,96), concatenated flat f32.

#define NEG_VAL (-1000000000.0f)

// Scratch (device globals -- no allocations allowed)
__device__ float g_E[2 * 33 * 96 * 128];   // node embeddings, row = g*33*96 + t*96 + i
__device__ float g_A[2 * 32 * 96 * 128];   // xne @ udW1[0:128]     row = g*32*96 + t*96 + i
__device__ float g_B[2 * 32 * 96 * 128];   // xce @ udW1[128:256]
__device__ float g_C[2 * 96 * 96 * 128];   // ee  @ udW1[256:288]   row = (g*96+i)*96 + j

// ---- f32x2 packed-FMA helpers (Blackwell) ----------------------------------
__device__ __forceinline__ void ffma2(unsigned long long& d, unsigned long long a,
                                      unsigned long long b) {
    asm("fma.rn.f32x2 %0, %1, %2, %0;" : "+l"(d) : "l"(a), "l"(b));
}
__device__ __forceinline__ unsigned long long packdup(float x) {
    unsigned long long r;
    asm("mov.b64 %0, {%1, %1};" : "=l"(r) : "f"(x));
    return r;
}
__device__ __forceinline__ void unpack2(float& lo, float& hi, unsigned long long v) {
    asm("mov.b64 {%0, %1}, %2;" : "=f"(lo), "=f"(hi) : "l"(v));
}

// ---------------------------------------------------------------------------
// Kernel 1: node embeddings  E = relu(relu(x @ neW1 + b1) @ neW2 + b2)
// ---------------------------------------------------------------------------
#define EROWS 8
__global__ void k_node_embed(const float* __restrict__ x,
                             const float* __restrict__ W1, const float* __restrict__ b1,
                             const float* __restrict__ W2, const float* __restrict__ b2) {
    int r0 = blockIdx.x * EROWS;
    int tid = threadIdx.x;  // 128
    __shared__ float xv[EROWS][128];
    __shared__ float y1[EROWS][128];

#pragma unroll
    for (int r = 0; r < EROWS; r++) {
        int idx = r0 + r;
        int g = idx / (33 * 96);
        int rem = idx % (33 * 96);
        int t = rem / 96;
        int i = rem % 96;
        xv[r][tid] = x[((g * 33 + t) * 128 + tid) * 192 + 96 * g + i];
    }
    __syncthreads();

    float acc[EROWS];
#pragma unroll
    for (int r = 0; r < EROWS; r++) acc[r] = b1[tid];
    for (int k = 0; k < 128; k++) {
        float w = W1[k * 128 + tid];
#pragma unroll
        for (int r = 0; r < EROWS; r++) acc[r] += xv[r][k] * w;
    }
#pragma unroll
    for (int r = 0; r < EROWS; r++) y1[r][tid] = fmaxf(acc[r], 0.0f);
    __syncthreads();

#pragma unroll
    for (int r = 0; r < EROWS; r++) acc[r] = b2[tid];
    for (int k = 0; k < 128; k++) {
        float w = W2[k * 128 + tid];
#pragma unroll
        for (int r = 0; r < EROWS; r++) acc[r] += y1[r][k] * w;
    }
#pragma unroll
    for (int r = 0; r < EROWS; r++) g_E[(r0 + r) * 128 + tid] = fmaxf(acc[r], 0.0f);
}

// ---------------------------------------------------------------------------
// Kernel 2: A/B projections + dist head.
// ---------------------------------------------------------------------------
#define PROWS 8
__global__ void k_proj_dist(const float* __restrict__ udW1,
                            const float* __restrict__ dpW1, const float* __restrict__ dpb1,
                            const float* __restrict__ dpW2, const float* __restrict__ dpb2,
                            const float* __restrict__ dpW3, const float* __restrict__ dpb3,
                            float* __restrict__ dist_out) {
    int r0 = blockIdx.x * PROWS;
    int tid = threadIdx.x;  // 128
    int g = r0 / (32 * 96);
    int rem = r0 % (32 * 96);
    int t = rem / 96;
    int i0 = rem % 96;

    __shared__ float Ec[PROWS][128];
    __shared__ float En[PROWS][128];
    __shared__ float y1d[PROWS][128];

    for (int e = tid; e < PROWS * 128; e += 128) {
        int r = e >> 7, k = e & 127;
        Ec[r][k] = g_E[((g * 33 + t) * 96 + i0 + r) * 128 + k];
        En[r][k] = g_E[((g * 33 + t + 1) * 96 + i0 + r) * 128 + k];
    }
    __syncthreads();

    float accA[PROWS], accB[PROWS], accD[PROWS];
#pragma unroll
    for (int r = 0; r < PROWS; r++) { accA[r] = 0.0f; accB[r] = 0.0f; accD[r] = 0.0f; }

    for (int k = 0; k < 128; k++) {
        float wa = udW1[k * 128 + tid];
        float wb = udW1[(128 + k) * 128 + tid];
        float wc = dpW1[k * 128 + tid];
        float wd = dpW1[(128 + k) * 128 + tid];
#pragma unroll
        for (int r = 0; r < PROWS; r++) {
            accA[r] += En[r][k] * wa;
            accB[r] += Ec[r][k] * wb;
            accD[r] += Ec[r][k] * wc + En[r][k] * wd;
        }
    }
    float db1 = dpb1[tid];
#pragma unroll
    for (int r = 0; r < PROWS; r++) {
        g_A[(r0 + r) * 128 + tid] = accA[r];
        g_B[(r0 + r) * 128 + tid] = accB[r];
        y1d[r][tid] = fmaxf(accD[r] + db1, 0.0f);
    }
    __syncthreads();

    int r = tid >> 4;
    int q = tid & 15;
    float s = 0.0f;
#pragma unroll
    for (int nn = 0; nn < 4; nn++) {
        int n = q * 4 + nn;
        float a = dpb2[n];
        for (int k = 0; k < 128; k++) a += y1d[r][k] * dpW2[k * 64 + n];
        s += fmaxf(a, 0.0f) * dpW3[n];
    }
#pragma unroll
    for (int off = 8; off; off >>= 1) s += __shfl_xor_sync(0xffffffffu, s, off);
    if (q == 0) dist_out[r0 + r] = s + dpb3[0];
}

// ---------------------------------------------------------------------------
// Kernel 3: edge MLP + C projection.
// ---------------------------------------------------------------------------
__global__ void k_ee_c(const float* __restrict__ edge_w,
                       const float* __restrict__ eeW1, const float* __restrict__ eeb1,
                       const float* __restrict__ eeW2, const float* __restrict__ eeb2,
                       const float* __restrict__ udW1) {
    int g = blockIdx.x / 96;
    int i = blockIdx.x % 96;
    int tid = threadIdx.x;  // 128

    __shared__ float l2s[96][33];
    __shared__ float w1s[32], b1s[32], b2s[32];
    __shared__ float w2s[32 * 32];
    __shared__ float w1cs[32 * 128];
    __shared__ float ews[96];

    if (tid < 32) { w1s[tid] = eeW1[tid]; b1s[tid] = eeb1[tid]; b2s[tid] = eeb2[tid]; }
    for (int e = tid; e < 1024; e += 128) w2s[e] = eeW2[e];
    for (int e = tid; e < 4096; e += 128) w1cs[e] = udW1[256 * 128 + e];
    if (tid < 96) ews[tid] = edge_w[(96 * g + i) * 192 + 96 * g + tid];
    __syncthreads();

    for (int e = tid; e < 96 * 32; e += 128) {
        int j = e >> 5, q = e & 31;
        float e0 = ews[j];
        float a = b2s[q];
#pragma unroll
        for (int p = 0; p < 32; p++) {
            float l1 = fmaxf(e0 * w1s[p] + b1s[p], 0.0f);
            a += l1 * w2s[p * 32 + q];
        }
        l2s[j][q] = fmaxf(a, 0.0f);
    }
    __syncthreads();

    float* Cout = g_C + (size_t)((g * 96 + i) * 96) * 128;
    for (int j = 0; j < 96; j++) {
        float a = 0.0f;
#pragma unroll
        for (int q = 0; q < 32; q++) a += l2s[j][q] * w1cs[q * 128 + tid];
        Cout[j * 128 + tid] = a;
    }
}

// ---------------------------------------------------------------------------
// Kernel 4 (dominant): per (g,t,i) compute logits[j=0..95].
//   h[j,k]   = relu(A[i,k] + B[j,k] + C[i,j,k] + b1[k])        (96 x 128)
//   y2[j,n]  = relu(h @ W2 + b2)                               (96 x 64)
//   logit[j] = y2 @ W3 + b3, masked where ew==0 && j!=i
//
// 256 threads: tx = tid&7 owns 8 n's split as two conflict-free quads
// {tx*4..tx*4+3} and {32+tx*4..32+tx*4+3}; ty = tid>>3 owns 3 j's.
// Accumulators are f32x2 pairs -> 12 FFMA2 per (thread,k).
// h tile stored [j][k] (stride 36) -> STS.128 writes, LDS.128 reads (4 k's).
// W2 read as ulonglong2 (natively packed f32x2 pairs).
// ---------------------------------------------------------------------------
__global__ void __launch_bounds__(256) k_logits(const float* __restrict__ edge_w,
                                                const float* __restrict__ udb1,
                                                const float* __restrict__ udW2,
                                                const float* __restrict__ udb2,
                                                const float* __restrict__ udW3,
                                                const float* __restrict__ udb3,
                                                float* __restrict__ out) {
    int bid = blockIdx.x;                 // g*32*96 + t*96 + i
    int g = bid / (32 * 96);
    int rem = bid % (32 * 96);
    int t = rem / 96;
    int i = rem % 96;
    int tid = threadIdx.x;
    int tx = tid & 7;
    int ty = tid >> 3;

    __shared__ float sW2[128 * 64];       // 32 KB
    __shared__ float sh[96 * 36];         // h tile [j][k0..k0+31 +pad], 13.5 KB
    __shared__ float sA[128];
    __shared__ float sW3[64];
    __shared__ float sb2[64];
    __shared__ float ews[96];

    for (int e = tid; e < 128 * 64 / 4; e += 256)
        reinterpret_cast<float4*>(sW2)[e] = reinterpret_cast<const float4*>(udW2)[e];
    if (tid < 128) sA[tid] = g_A[bid * 128 + tid] + udb1[tid];
    if (tid >= 128 && tid < 192) { int n = tid - 128; sW3[n] = udW3[n]; sb2[n] = udb2[n]; }
    if (tid >= 160) {
        int j = tid - 160;  // 96 entries
        ews[j] = edge_w[(96 * g + i) * 192 + 96 * g + j];
    }

    const float* Bb = g_B + (size_t)((g * 32 + t) * 96) * 128;
    const float* Cb = g_C + (size_t)((g * 96 + i) * 96) * 128;

    unsigned long long acc[3][4];
#pragma unroll
    for (int jj = 0; jj < 3; jj++)
#pragma unroll
        for (int p = 0; p < 4; p++) acc[jj][p] = 0ULL;

    const float4* sh4 = reinterpret_cast<const float4*>(sh);

    for (int kt = 0; kt < 4; kt++) {
        __syncthreads();  // guards sh reuse (and initial smem loads on kt==0)
        // Build h tile: 96 j x 32 k, as 768 float4 chunks (3 per thread)
#pragma unroll
        for (int it = 0; it < 3; it++) {
            int e = tid + it * 256;
            int j = e >> 3, kq = e & 7;
            int k0 = kt * 32 + kq * 4;
            float4 b4 = *reinterpret_cast<const float4*>(Bb + j * 128 + k0);
            float4 c4 = *reinterpret_cast<const float4*>(Cb + j * 128 + k0);
            float4 a4 = *reinterpret_cast<const float4*>(sA + k0);
            float4 v;
            v.x = fmaxf(a4.x + b4.x + c4.x, 0.0f);
            v.y = fmaxf(a4.y + b4.y + c4.y, 0.0f);
            v.z = fmaxf(a4.z + b4.z + c4.z, 0.0f);
            v.w = fmaxf(a4.w + b4.w + c4.w, 0.0f);
            *reinterpret_cast<float4*>(sh + j * 36 + kq * 4) = v;
        }
        __syncthreads();

#pragma unroll
        for (int k4 = 0; k4 < 8; k4++) {
            float h0a[4], h1a[4], h2a[4];
            *reinterpret_cast<float4*>(h0a) = sh4[(ty * 3 + 0) * 9 + k4];
            *reinterpret_cast<float4*>(h1a) = sh4[(ty * 3 + 1) * 9 + k4];
            *reinterpret_cast<float4*>(h2a) = sh4[(ty * 3 + 2) * 9 + k4];
#pragma unroll
            for (int kk = 0; kk < 4; kk++) {
                const float* wrow = sW2 + (kt * 32 + k4 * 4 + kk) * 64;
                ulonglong2 wa = *reinterpret_cast<const ulonglong2*>(wrow + tx * 4);
                ulonglong2 wb = *reinterpret_cast<const ulonglong2*>(wrow + 32 + tx * 4);
                unsigned long long hd0 = packdup(h0a[kk]);
                unsigned long long hd1 = packdup(h1a[kk]);
                unsigned long long hd2 = packdup(h2a[kk]);
                ffma2(acc[0][0], hd0, wa.x); ffma2(acc[0][1], hd0, wa.y);
                ffma2(acc[0][2], hd0, wb.x); ffma2(acc[0][3], hd0, wb.y);
                ffma2(acc[1][0], hd1, wa.x); ffma2(acc[1][1], hd1, wa.y);
                ffma2(acc[1][2], hd1, wb.x); ffma2(acc[1][3], hd1, wb.y);
                ffma2(acc[2][0], hd2, wa.x); ffma2(acc[2][1], hd2, wa.y);
                ffma2(acc[2][2], hd2, wb.x); ffma2(acc[2][3], hd2, wb.y);
            }
        }
    }

    float b3 = udb3[0];
#pragma unroll
    for (int jj = 0; jj < 3; jj++) {
        float s = 0.0f;
#pragma unroll
        for (int p = 0; p < 4; p++) {
            int n = (p < 2) ? (tx * 4 + p * 2) : (32 + tx * 4 + (p - 2) * 2);
            float f0, f1;
            unpack2(f0, f1, acc[jj][p]);
            s += fmaxf(f0 + sb2[n], 0.0f) * sW3[n];
            s += fmaxf(f1 + sb2[n + 1], 0.0f) * sW3[n + 1];
        }
#pragma unroll
        for (int off = 4; off; off >>= 1) s += __shfl_xor_sync(0xffffffffu, s, off);
        if (tx == 0) {
            int j = ty * 3 + jj;
            float L = s + b3;
            if (ews[j] == 0.0f && j != i) L = NEG_VAL;
            out[(size_t)bid * 96 + j] = L;
        }
    }
}

// ---------------------------------------------------------------------------
// Launch
// ---------------------------------------------------------------------------
extern "C" void kernel_launch(void* const* d_in, const int* in_sizes, int n_in,
                              void* d_out, int out_size) {
    int w0 = n_in - 20;
    const float* x      = (const float*)d_in[0];
    const float* edge_w = (const float*)d_in[1];
    const float* neW1 = (const float*)d_in[w0 + 0];
    const float* neb1 = (const float*)d_in[w0 + 1];
    const float* neW2 = (const float*)d_in[w0 + 2];
    const float* neb2 = (const float*)d_in[w0 + 3];
    const float* eeW1 = (const float*)d_in[w0 + 4];
    const float* eeb1 = (const float*)d_in[w0 + 5];
    const float* eeW2 = (const float*)d_in[w0 + 6];
    const float* eeb2 = (const float*)d_in[w0 + 7];
    const float* udW1 = (const float*)d_in[w0 + 8];
    const float* udb1 = (const float*)d_in[w0 + 9];
    const float* udW2 = (const float*)d_in[w0 + 10];
    const float* udb2 = (const float*)d_in[w0 + 11];
    const float* udW3 = (const float*)d_in[w0 + 12];
    const float* udb3 = (const float*)d_in[w0 + 13];
    const float* dpW1 = (const float*)d_in[w0 + 14];
    const float* dpb1 = (const float*)d_in[w0 + 15];
    const float* dpW2 = (const float*)d_in[w0 + 16];
    const float* dpb2 = (const float*)d_in[w0 + 17];
    const float* dpW3 = (const float*)d_in[w0 + 18];
    const float* dpb3 = (const float*)d_in[w0 + 19];

    float* out = (float*)d_out;
    const int CLASS_N = 2 * 32 * 96 * 96;  // 589824
    float* dist_out = out + CLASS_N;

    k_node_embed<<<6336 / EROWS, 128>>>(x, neW1, neb1, neW2, neb2);
    k_proj_dist<<<6144 / PROWS, 128>>>(udW1, dpW1, dpb1, dpW2, dpb2, dpW3, dpb3, dist_out);
    k_ee_c<<<2 * 96, 128>>>(edge_w, eeW1, eeb1, eeW2, eeb2, udW1);
    k_logits<<<2 * 32 * 96, 256>>>(edge_w, udb1, udW2, udb2, udW3, udb3, out);
}